// round 8
// baseline (speedup 1.0000x reference)
#include <cuda_runtime.h>
#include <cuda_bf16.h>

#define Bq 256
#define Tq 512
#define Kq 128
#define SOS 0
#define EOSI 1
#define NSM 152   // GB300 SMs; wave-2 CTA (bid+152) co-resides with bid
#define PPAD 136  // padded p row: halves at +0 and +272B -> disjoint banks

__device__ float g_E[Kq * Kq];   // exp(trans), row-major
__device__ int   g_perm[Bq];     // batch index sorted by descending length
__device__ int   g_len[Bq];      // sequence length per batch

// ---------------- prep: E = exp(trans), lengths, rank permutation ----------------
__global__ void prep_kernel(const float* __restrict__ trans,
                            const float* __restrict__ mask) {
    if (blockIdx.x < 64) {
        int i = blockIdx.x * 256 + threadIdx.x;
        g_E[i] = expf(trans[i]);          // exp(-10000) -> exactly 0
    } else {
        __shared__ int slen[Bq];
        int tid = threadIdx.x, w = tid >> 5, lane = tid & 31;
        for (int r = w; r < Bq; r += 8) {
            float s = 0.f;
            const float* mr = mask + (size_t)r * Tq;
            for (int i = lane; i < Tq; i += 32) s += mr[i];
            #pragma unroll
            for (int o = 16; o > 0; o >>= 1) s += __shfl_xor_sync(0xffffffffu, s, o);
            if (lane == 0) slen[r] = (int)(s + 0.5f);
        }
        __syncthreads();
        int L = slen[tid];
        g_len[tid] = L;
        int rank = 0;
        for (int j = 0; j < Bq; j++) {
            int Lj = slen[j];
            rank += (Lj > L) || (Lj == L && j < tid);
        }
        g_perm[rank] = tid;
    }
}

__device__ __forceinline__ unsigned long long pk2(float a, float b) {
    return (unsigned long long)__float_as_uint(a) |
           ((unsigned long long)__float_as_uint(b) << 32);
}
__device__ __forceinline__ void fma2(unsigned long long& d,
                                     unsigned long long a, unsigned long long b) {
    asm("fma.rn.f32x2 %0, %1, %2, %0;" : "+l"(d) : "l"(a), "l"(b));
}
__device__ __forceinline__ void add2(unsigned long long& d, unsigned long long a) {
    asm("add.rn.f32x2 %0, %0, %1;" : "+l"(d) : "l"(a));
}
__device__ __forceinline__ float warp_max_pos(float v) {
    unsigned u = __float_as_uint(v), r;
    asm("redux.sync.max.u32 %0, %1, 0xffffffff;" : "=r"(r) : "r"(u));
    return __uint_as_float(r);     // valid for non-negative floats
}

// state j lives at padded index (j<64 ? j : j+4)
__device__ __forceinline__ int pidx(int j) { return j + ((j >> 6) << 2); }

// ---------------- main CRF scan: 256 threads, lane-pair per output row ----------------
__global__ void __launch_bounds__(256, 2) crf_main_kernel(
    const float* __restrict__ h, float* __restrict__ out)
{
    int bid = blockIdx.x;
    // Solo SMs (bids 104..151, no wave-2 partner) take the 48 longest
    // sequences; pair (i, i+152) takes complementary length ranks.
    int rank;
    if (bid >= 104 && bid < NSM) rank = bid - 104;          // ranks 0..47 solo
    else if (bid < 104)          rank = 48 + bid;           // 48..151
    else                         rank = 407 - bid;          // 255..152
    int b = g_perm[rank] & (Bq - 1);
    int L = g_len[b];

    int tid  = threadIdx.x;
    int w    = tid >> 5, lane = tid & 31;
    int row  = (w << 4) | (lane >> 1);   // output row (state k)
    int half = lane & 1;                 // j-half of E[row,:]

    __shared__ __align__(16) float pbuf[2][PPAD];
    __shared__ __align__(16) float wred4[4][8];   // per-warp max, consumed 2 steps later

    // 32 packed f32x2 regs: E[row, half*64 .. half*64+63]
    unsigned long long e2[32];
    {
        const float4* er = reinterpret_cast<const float4*>(g_E + row * Kq + half * 64);
        #pragma unroll
        for (int i = 0; i < 16; i++) {
            float4 f = er[i];
            e2[2 * i]     = pk2(f.x, f.y);
            e2[2 * i + 1] = pk2(f.z, f.w);
        }
    }

    if (tid < Kq) pbuf[0][pidx(tid)] = (tid == SOS) ? 1.0f : 0.0f;
    if (tid < 8) { wred4[2][tid] = 1.0f; wred4[3][tid] = 1.0f; }  // mx for t=0,1
    float C = 0.0f;

    const float* hb = h + (size_t)b * Tq * Kq + row;  // lane pair loads same value
    float ehc = __expf(hb[0]);                        // exp(h_0)
    float hy  = (1 < Tq) ? hb[(size_t)1 * Kq] : 0.f;  // h_1
    float hx  = 0.f;
    __syncthreads();

    int t = 0;

    // One scan step. LOADR receives h[t+2]; EXPR holds h[t+1] (exp'd here).
#define STEP(LOADR, EXPR)                                                        \
    {                                                                            \
        int tp = t + 2;                                                          \
        LOADR = (tp < Tq) ? hb[(size_t)tp * Kq] : 0.f;                           \
        float ehn = __expf(EXPR);                                                \
        /* off-path: normalization deferred from step t-2 */                     \
        float4 wa = *reinterpret_cast<const float4*>(&wred4[(t - 2) & 3][0]);    \
        float4 wbv = *reinterpret_cast<const float4*>(&wred4[(t - 2) & 3][4]);   \
        float mx = fmaxf(fmaxf(fmaxf(wa.x, wa.y), fmaxf(wa.z, wa.w)),            \
                         fmaxf(fmaxf(wbv.x, wbv.y), fmaxf(wbv.z, wbv.w)));       \
        float ef = __fdividef(ehc, mx);                                          \
        C += __logf(mx);                                                         \
        unsigned long long acc0 = 0, acc1 = 0, acc2 = 0, acc3 = 0;               \
        const ulonglong2* pu = reinterpret_cast<const ulonglong2*>(              \
            pbuf[t & 1] + half * 68);                                            \
        _Pragma("unroll")                                                        \
        for (int i = 0; i < 8; i++) {                                            \
            ulonglong2 qa = pu[2 * i];                                           \
            ulonglong2 qb = pu[2 * i + 1];                                       \
            fma2(acc0, e2[4 * i],     qa.x);                                     \
            fma2(acc1, e2[4 * i + 1], qa.y);                                     \
            fma2(acc2, e2[4 * i + 2], qb.x);                                     \
            fma2(acc3, e2[4 * i + 3], qb.y);                                     \
        }                                                                        \
        add2(acc0, acc2); add2(acc1, acc3);                                      \
        add2(acc0, acc1);                                                        \
        float s = __uint_as_float((unsigned)acc0) +                              \
                  __uint_as_float((unsigned)(acc0 >> 32));                       \
        float v = (s + __shfl_xor_sync(0xffffffffu, s, 1)) * ef;                 \
        if (half == 0) pbuf[(t + 1) & 1][pidx(row)] = v;                         \
        float wm = warp_max_pos(v);                                              \
        if (lane == 0) wred4[t & 3][w] = wm;                                     \
        __syncthreads();                                                         \
        ehc = ehn;                                                               \
        t++;                                                                     \
    }

    while (t + 2 <= L) {
        STEP(hx, hy);    // step t:   loads h[t+2] into hx, exps hy=h[t+1]
        STEP(hy, hx);    // step t+1: loads h[t+3] into hy, exps hx=h[t+2]
    }
    if (t < L) STEP(hx, hy);
#undef STEP

    // out[b] = C + log( sum_k p_raw[k] * E[EOS,k] )
    float val = 0.f;
    if (tid < Kq) val = pbuf[t & 1][pidx(tid)] * g_E[EOSI * Kq + tid];
    #pragma unroll
    for (int o = 16; o > 0; o >>= 1)
        val += __shfl_xor_sync(0xffffffffu, val, o);
    if (lane == 0 && w < 4) wred4[0][w] = val;
    __syncthreads();
    if (tid == 0)
        out[b] = C + __logf(wred4[0][0] + wred4[0][1] + wred4[0][2] + wred4[0][3]);
}

extern "C" void kernel_launch(void* const* d_in, const int* in_sizes, int n_in,
                              void* d_out, int out_size) {
    const float* h     = (const float*)d_in[0];
    const float* trans = (const float*)d_in[1];
    const float* mask  = (const float*)d_in[2];
    float* out = (float*)d_out;
    (void)in_sizes; (void)n_in; (void)out_size;

    prep_kernel<<<65, 256>>>(trans, mask);
    crf_main_kernel<<<Bq, 256>>>(h, out);
}

// round 9
// speedup vs baseline: 1.2621x; 1.2621x over previous
#include <cuda_runtime.h>
#include <cuda_bf16.h>

#define Bq 256
#define Tq 512
#define Kq 128
#define SOS 0
#define EOSI 1
#define NSM 152   // GB300 SMs; wave-2 CTA (bid+152) co-resides with bid

__device__ float g_E[Kq * Kq];   // exp(trans), row-major
__device__ int   g_perm[Bq];     // batch index sorted by descending length
__device__ int   g_len[Bq];      // sequence length per batch

// ---------------- prep: E = exp(trans), lengths, rank permutation ----------------
__global__ void prep_kernel(const float* __restrict__ trans,
                            const float* __restrict__ mask) {
    if (blockIdx.x < 64) {
        int i = blockIdx.x * 256 + threadIdx.x;
        g_E[i] = expf(trans[i]);          // exp(-10000) -> exactly 0
    } else {
        __shared__ int slen[Bq];
        int tid = threadIdx.x, w = tid >> 5, lane = tid & 31;
        for (int r = w; r < Bq; r += 8) {
            float s = 0.f;
            const float* mr = mask + (size_t)r * Tq;
            for (int i = lane; i < Tq; i += 32) s += mr[i];
            #pragma unroll
            for (int o = 16; o > 0; o >>= 1) s += __shfl_xor_sync(0xffffffffu, s, o);
            if (lane == 0) slen[r] = (int)(s + 0.5f);
        }
        __syncthreads();
        int L = slen[tid];
        g_len[tid] = L;
        int rank = 0;
        for (int j = 0; j < Bq; j++) {
            int Lj = slen[j];
            rank += (Lj > L) || (Lj == L && j < tid);
        }
        g_perm[rank] = tid;
    }
}

__device__ __forceinline__ unsigned long long pk2(float a, float b) {
    return (unsigned long long)__float_as_uint(a) |
           ((unsigned long long)__float_as_uint(b) << 32);
}
__device__ __forceinline__ void fma2(unsigned long long& d,
                                     unsigned long long a, unsigned long long b) {
    asm("fma.rn.f32x2 %0, %1, %2, %0;" : "+l"(d) : "l"(a), "l"(b));
}
__device__ __forceinline__ void add2(unsigned long long& d, unsigned long long a) {
    asm("add.rn.f32x2 %0, %0, %1;" : "+l"(d) : "l"(a));
}

// ---------------- main CRF scan: 128 threads, 1 thread per output row ----------------
__global__ void __launch_bounds__(128, 2) crf_main_kernel(
    const float* __restrict__ h, float* __restrict__ out)
{
    int bid = blockIdx.x;
    // Solo SMs (bids 104..151, no wave-2 partner) take the 48 longest
    // sequences; pair (i, i+152) takes complementary length ranks.
    int rank;
    if (bid >= 104 && bid < NSM) rank = bid - 104;          // ranks 0..47 solo
    else if (bid < 104)          rank = 48 + bid;           // 48..151
    else                         rank = 407 - bid;          // 255..152
    int b = g_perm[rank] & (Bq - 1);
    int L = g_len[b];

    int k = threadIdx.x;
    int lane = k & 31, w = k >> 5;

    __shared__ __align__(16) float pbuf[2][Kq];
    __shared__ float fred[4];

    // thread k owns E row k in registers, packed for f32x2
    unsigned long long e2[Kq / 2];
    {
        const float4* er = reinterpret_cast<const float4*>(g_E + k * Kq);
        #pragma unroll
        for (int i = 0; i < Kq / 4; i++) {
            float4 f = er[i];
            e2[2 * i]     = pk2(f.x, f.y);
            e2[2 * i + 1] = pk2(f.z, f.w);
        }
    }

    float C = 0.0f;
    const float* hb = h + (size_t)b * Tq * Kq + k;

    // initial loads (Tq=512 always, so hb[0..2] in-bounds regardless of L)
    float ha0 = hb[0];
    float ha1 = hb[(size_t)1 * Kq];
    float ha2 = hb[(size_t)2 * Kq];

    // ---- peel step t=0: P_1[k] = e^{h0[k]} * E[k,SOS], pivot = P_0[SOS] = 1
    float ehc = __expf(ha0);
    pbuf[1][k] = __uint_as_float((unsigned)e2[0]) * ehc;   // E[k,0] * e^{h0}
    __syncthreads();

    ehc = __expf(ha1);   // exp(h_1) for step t=1
    float hy = ha2;      // h_2 (exp'd at t=1 for t=2)
    float hx = 0.f;
    int t = 1;

    // One scan step. LOADR receives h[t+2]; EXPR holds h[t+1] (exp'd here).
    // Pivot normalization: scale = p[2] (raw), extracted from the first LDS.
#define STEP(LOADR, EXPR)                                                        \
    {                                                                            \
        int tp = t + 2;                                                          \
        LOADR = (tp < Tq) ? hb[(size_t)tp * Kq] : 0.f;                           \
        float ehn = __expf(EXPR);                                                \
        const ulonglong2* pu =                                                   \
            reinterpret_cast<const ulonglong2*>(pbuf[t & 1]);                    \
        ulonglong2 q0 = pu[0];                                                   \
        float pivot = __uint_as_float((unsigned)q0.y);   /* p[2], > 0 for t>=1 */\
        float ef = __fdividef(ehc, pivot);               /* ready early */       \
        C += __logf(pivot);                              /* off the FMA path */  \
        unsigned long long acc0 = 0, acc1 = 0, acc2 = 0, acc3 = 0;               \
        fma2(acc0, e2[0], q0.x);                                                 \
        fma2(acc1, e2[1], q0.y);                                                 \
        {                                                                        \
            ulonglong2 qb0 = pu[1];                                              \
            fma2(acc2, e2[2], qb0.x);                                            \
            fma2(acc3, e2[3], qb0.y);                                            \
        }                                                                        \
        _Pragma("unroll")                                                        \
        for (int i = 1; i < 16; i++) {                                           \
            ulonglong2 qa = pu[2 * i];                                           \
            ulonglong2 qb = pu[2 * i + 1];                                       \
            fma2(acc0, e2[4 * i],     qa.x);                                     \
            fma2(acc1, e2[4 * i + 1], qa.y);                                     \
            fma2(acc2, e2[4 * i + 2], qb.x);                                     \
            fma2(acc3, e2[4 * i + 3], qb.y);                                     \
        }                                                                        \
        add2(acc0, acc2); add2(acc1, acc3);                                      \
        add2(acc0, acc1);                                                        \
        float v = (__uint_as_float((unsigned)acc0) +                             \
                   __uint_as_float((unsigned)(acc0 >> 32))) * ef;                \
        pbuf[(t + 1) & 1][k] = v;                                                \
        __syncthreads();                                                         \
        ehc = ehn;                                                               \
        t++;                                                                     \
    }

    while (t + 2 <= L) {
        STEP(hx, hy);    // step t:   loads h[t+2] into hx, exps hy=h[t+1]
        STEP(hy, hx);    // step t+1: loads h[t+3] into hy, exps hx=h[t+2]
    }
    if (t < L) STEP(hx, hy);
#undef STEP

    // out[b] = C + log( sum_k P_L[k] * E[EOS,k] )
    float val = pbuf[t & 1][k] * g_E[EOSI * Kq + k];
    #pragma unroll
    for (int o = 16; o > 0; o >>= 1)
        val += __shfl_xor_sync(0xffffffffu, val, o);
    if (lane == 0) fred[w] = val;
    __syncthreads();
    if (k == 0)
        out[b] = C + __logf(fred[0] + fred[1] + fred[2] + fred[3]);
}

extern "C" void kernel_launch(void* const* d_in, const int* in_sizes, int n_in,
                              void* d_out, int out_size) {
    const float* h     = (const float*)d_in[0];
    const float* trans = (const float*)d_in[1];
    const float* mask  = (const float*)d_in[2];
    float* out = (float*)d_out;
    (void)in_sizes; (void)n_in; (void)out_size;

    prep_kernel<<<65, 256>>>(trans, mask);
    crf_main_kernel<<<Bq, Kq>>>(h, out);
}

// round 10
// speedup vs baseline: 1.2781x; 1.0127x over previous
#include <cuda_runtime.h>
#include <cuda_bf16.h>

#define Bq 256
#define Tq 512
#define Kq 128
#define SOS 0
#define EOSI 1
#define NSM 152   // GB300 SMs; wave-2 CTA (bid+152) co-resides with bid

__device__ float g_E[Kq * Kq];   // exp(trans), row-major
__device__ int   g_perm[Bq];     // batch index sorted by descending length
__device__ int   g_len[Bq];      // sequence length per batch

// ---------------- prep: E = exp(trans), lengths, rank permutation ----------------
__global__ void prep_kernel(const float* __restrict__ trans,
                            const float* __restrict__ mask) {
    if (blockIdx.x < 64) {
        int i = blockIdx.x * 256 + threadIdx.x;
        g_E[i] = expf(trans[i]);          // exp(-10000) -> exactly 0
    } else {
        __shared__ int slen[Bq];
        int tid = threadIdx.x, w = tid >> 5, lane = tid & 31;
        for (int r = w; r < Bq; r += 8) {
            float s = 0.f;
            const float* mr = mask + (size_t)r * Tq;
            for (int i = lane; i < Tq; i += 32) s += mr[i];
            #pragma unroll
            for (int o = 16; o > 0; o >>= 1) s += __shfl_xor_sync(0xffffffffu, s, o);
            if (lane == 0) slen[r] = (int)(s + 0.5f);
        }
        __syncthreads();
        int L = slen[tid];
        g_len[tid] = L;
        int rank = 0;
        for (int j = 0; j < Bq; j++) {
            int Lj = slen[j];
            rank += (Lj > L) || (Lj == L && j < tid);
        }
        g_perm[rank] = tid;
    }
}

// ---------------- main CRF scan: 128 threads, 1 thread per output row ----------------
__global__ void __launch_bounds__(128, 2) crf_main_kernel(
    const float* __restrict__ h, float* __restrict__ out)
{
    int bid = blockIdx.x;
    // Solo SMs (bids 104..151, no wave-2 partner) take the 48 longest
    // sequences; pair (i, i+152) takes complementary length ranks.
    int rank;
    if (bid >= 104 && bid < NSM) rank = bid - 104;          // ranks 0..47 solo
    else if (bid < 104)          rank = 48 + bid;           // 48..151
    else                         rank = 407 - bid;          // 255..152
    int b = g_perm[rank] & (Bq - 1);
    int L = g_len[b];

    int k = threadIdx.x;
    int lane = k & 31, w = k >> 5;

    __shared__ __align__(16) float pbuf[2][Kq];
    __shared__ float fred[4];

    // thread k owns E row k in 128 scalar registers
    float e[Kq];
    {
        const float4* er = reinterpret_cast<const float4*>(g_E + k * Kq);
        #pragma unroll
        for (int i = 0; i < Kq / 4; i++) {
            float4 f = er[i];
            e[4 * i]     = f.x;
            e[4 * i + 1] = f.y;
            e[4 * i + 2] = f.z;
            e[4 * i + 3] = f.w;
        }
    }

    float C = 0.0f;
    const float* hb = h + (size_t)b * Tq * Kq + k;

    // initial loads (Tq=512 always, so hb[0..2] in-bounds regardless of L)
    float ha0 = hb[0];
    float ha1 = hb[(size_t)1 * Kq];
    float ha2 = hb[(size_t)2 * Kq];

    // ---- peel step t=0: P_1[k] = e^{h0[k]} * E[k,SOS], pivot = P_0[SOS] = 1
    float ehc = __expf(ha0);
    pbuf[1][k] = e[0] * ehc;               // E[k,0] * e^{h0}
    __syncthreads();

    ehc = __expf(ha1);   // exp(h_1) for step t=1
    float hy = ha2;      // h_2 (exp'd at t=1 for t=2)
    float hx = 0.f;
    int t = 1;

    // One scan step. LOADR receives h[t+2]; EXPR holds h[t+1] (exp'd here).
    // Pivot normalization: scale = p[2] (raw), extracted from the first LDS.
#define STEP(LOADR, EXPR)                                                        \
    {                                                                            \
        int tp = t + 2;                                                          \
        LOADR = (tp < Tq) ? hb[(size_t)tp * Kq] : 0.f;                           \
        float ehn = __expf(EXPR);                                                \
        const float4* pu = reinterpret_cast<const float4*>(pbuf[t & 1]);         \
        float4 q0 = pu[0];                                                       \
        float pivot = q0.z;                              /* p[2], > 0 for t>=1 */\
        float ef = __fdividef(ehc, pivot);               /* off the FMA path */  \
        C += __logf(pivot);                              /* off the FMA path */  \
        float a0, a1, a2, a3, a4, a5, a6, a7;                                    \
        a0 = e[0] * q0.x;  a1 = e[1] * q0.y;                                     \
        a2 = e[2] * q0.z;  a3 = e[3] * q0.w;                                     \
        {                                                                        \
            float4 q1 = pu[1];                                                   \
            a4 = e[4] * q1.x;  a5 = e[5] * q1.y;                                 \
            a6 = e[6] * q1.z;  a7 = e[7] * q1.w;                                 \
        }                                                                        \
        _Pragma("unroll")                                                        \
        for (int i = 1; i < 16; i++) {                                           \
            float4 qa = pu[2 * i];                                               \
            float4 qb = pu[2 * i + 1];                                           \
            a0 = fmaf(e[8 * i],     qa.x, a0);                                   \
            a1 = fmaf(e[8 * i + 1], qa.y, a1);                                   \
            a2 = fmaf(e[8 * i + 2], qa.z, a2);                                   \
            a3 = fmaf(e[8 * i + 3], qa.w, a3);                                   \
            a4 = fmaf(e[8 * i + 4], qb.x, a4);                                   \
            a5 = fmaf(e[8 * i + 5], qb.y, a5);                                   \
            a6 = fmaf(e[8 * i + 6], qb.z, a6);                                   \
            a7 = fmaf(e[8 * i + 7], qb.w, a7);                                   \
        }                                                                        \
        float s0 = a0 + a4, s1 = a1 + a5, s2 = a2 + a6, s3 = a3 + a7;            \
        float v = ((s0 + s1) + (s2 + s3)) * ef;                                  \
        pbuf[(t + 1) & 1][k] = v;                                                \
        __syncthreads();                                                         \
        ehc = ehn;                                                               \
        t++;                                                                     \
    }

    while (t + 2 <= L) {
        STEP(hx, hy);    // step t:   loads h[t+2] into hx, exps hy=h[t+1]
        STEP(hy, hx);    // step t+1: loads h[t+3] into hy, exps hx=h[t+2]
    }
    if (t < L) STEP(hx, hy);
#undef STEP

    // out[b] = C + log( sum_k P_L[k] * E[EOS,k] )
    float val = pbuf[t & 1][k] * g_E[EOSI * Kq + k];
    #pragma unroll
    for (int o = 16; o > 0; o >>= 1)
        val += __shfl_xor_sync(0xffffffffu, val, o);
    if (lane == 0) fred[w] = val;
    __syncthreads();
    if (k == 0)
        out[b] = C + __logf(fred[0] + fred[1] + fred[2] + fred[3]);
}

extern "C" void kernel_launch(void* const* d_in, const int* in_sizes, int n_in,
                              void* d_out, int out_size) {
    const float* h     = (const float*)d_in[0];
    const float* trans = (const float*)d_in[1];
    const float* mask  = (const float*)d_in[2];
    float* out = (float*)d_out;
    (void)in_sizes; (void)n_in; (void)out_size;

    prep_kernel<<<65, 256>>>(trans, mask);
    crf_main_kernel<<<Bq, Kq>>>(h, out);
}

// round 11
// speedup vs baseline: 1.5115x; 1.1826x over previous
#include <cuda_runtime.h>
#include <cuda_bf16.h>

#define Bq 256
#define Tq 512
#define Kq 128
#define SOS 0
#define EOSI 1
#define NCTA 148   // <= GB300 SM count: every CTA lands on its own SM (wave 1)
#define NSOLO 40   // 40 solo + 108 sequential pairs = 40 + 216 = 256 batches

__device__ float g_E[Kq * Kq];   // exp(trans), row-major
__device__ int   g_perm[Bq];     // batch index sorted by descending length
__device__ int   g_len[Bq];      // sequence length per batch

// ---------------- prep: E = exp(trans), lengths, rank permutation ----------------
__global__ void prep_kernel(const float* __restrict__ trans,
                            const float* __restrict__ mask) {
    if (blockIdx.x < 64) {
        int i = blockIdx.x * 256 + threadIdx.x;
        g_E[i] = expf(trans[i]);          // exp(-10000) -> exactly 0
    } else {
        __shared__ int slen[Bq];
        int tid = threadIdx.x, w = tid >> 5, lane = tid & 31;
        for (int r = w; r < Bq; r += 8) {
            float s = 0.f;
            const float* mr = mask + (size_t)r * Tq;
            for (int i = lane; i < Tq; i += 32) s += mr[i];
            #pragma unroll
            for (int o = 16; o > 0; o >>= 1) s += __shfl_xor_sync(0xffffffffu, s, o);
            if (lane == 0) slen[r] = (int)(s + 0.5f);
        }
        __syncthreads();
        int L = slen[tid];
        g_len[tid] = L;
        int rank = 0;
        for (int j = 0; j < Bq; j++) {
            int Lj = slen[j];
            rank += (Lj > L) || (Lj == L && j < tid);
        }
        g_perm[rank] = tid;
    }
}

__device__ __forceinline__ unsigned long long pk2(float a, float b) {
    return (unsigned long long)__float_as_uint(a) |
           ((unsigned long long)__float_as_uint(b) << 32);
}
__device__ __forceinline__ void fma2(unsigned long long& d,
                                     unsigned long long a, unsigned long long b) {
    asm("fma.rn.f32x2 %0, %1, %2, %0;" : "+l"(d) : "l"(a), "l"(b));
}
__device__ __forceinline__ void add2(unsigned long long& d, unsigned long long a) {
    asm("add.rn.f32x2 %0, %0, %1;" : "+l"(d) : "l"(a));
}

// ---------------- main CRF scan: one CTA per SM, batches run back-to-back ------------
__global__ void __launch_bounds__(128, 1) crf_main_kernel(
    const float* __restrict__ h, float* __restrict__ out)
{
    int c = blockIdx.x;
    int k = threadIdx.x;
    int lane = k & 31, w = k >> 5;

    // Work list: CTA c<NSOLO -> 1 longest-rank batch; else 2 complementary ranks.
    int nb, r0, r1;
    if (c < NSOLO) { nb = 1; r0 = c;          r1 = 0; }
    else           { nb = 2; r0 = NSOLO + (c - NSOLO); r1 = 255 - (c - NSOLO); }

    __shared__ __align__(16) float pbuf[2][Kq];
    __shared__ float fred[4];

    // thread k owns E row k in registers, packed for f32x2 (loaded once)
    unsigned long long e2[Kq / 2];
    {
        const float4* er = reinterpret_cast<const float4*>(g_E + k * Kq);
        #pragma unroll
        for (int i = 0; i < Kq / 4; i++) {
            float4 f = er[i];
            e2[2 * i]     = pk2(f.x, f.y);
            e2[2 * i + 1] = pk2(f.z, f.w);
        }
    }
    float eEOS = g_E[EOSI * Kq + k];

    for (int bi = 0; bi < nb; bi++) {
        int b = g_perm[bi == 0 ? r0 : r1] & (Bq - 1);
        int L = g_len[b];

        float C = 0.0f;
        const float* hb = h + (size_t)b * Tq * Kq + k;

        float ha0 = hb[0];
        float ha1 = hb[(size_t)1 * Kq];
        float ha2 = hb[(size_t)2 * Kq];

        // ---- peel step t=0: P_1[k] = e^{h0[k]} * E[k,SOS], pivot = 1
        float ehc = __expf(ha0);
        pbuf[1][k] = __uint_as_float((unsigned)e2[0]) * ehc;   // E[k,0]*e^{h0}
        __syncthreads();

        ehc = __expf(ha1);   // exp(h_1) for step t=1
        float hy = ha2;      // h_2 (exp'd at t=1 for t=2)
        float hx = 0.f;
        int t = 1;

        // One scan step. LOADR receives h[t+2]; EXPR holds h[t+1] (exp'd here).
        // Pivot normalization: scale = p[2] (raw), from the first LDS.
#define STEP(LOADR, EXPR)                                                        \
        {                                                                        \
            int tp = t + 2;                                                      \
            LOADR = (tp < Tq) ? hb[(size_t)tp * Kq] : 0.f;                       \
            float ehn = __expf(EXPR);                                            \
            const ulonglong2* pu =                                               \
                reinterpret_cast<const ulonglong2*>(pbuf[t & 1]);                \
            ulonglong2 q0 = pu[0];                                               \
            float pivot = __uint_as_float((unsigned)q0.y);  /* p[2] > 0 */       \
            float ef = __fdividef(ehc, pivot);              /* off FMA path */   \
            C += __logf(pivot);                             /* off FMA path */   \
            unsigned long long acc0 = 0, acc1 = 0, acc2 = 0, acc3 = 0;           \
            fma2(acc0, e2[0], q0.x);                                             \
            fma2(acc1, e2[1], q0.y);                                             \
            {                                                                    \
                ulonglong2 qb0 = pu[1];                                          \
                fma2(acc2, e2[2], qb0.x);                                        \
                fma2(acc3, e2[3], qb0.y);                                        \
            }                                                                    \
            _Pragma("unroll")                                                    \
            for (int i = 1; i < 16; i++) {                                       \
                ulonglong2 qa = pu[2 * i];                                       \
                ulonglong2 qb = pu[2 * i + 1];                                   \
                fma2(acc0, e2[4 * i],     qa.x);                                 \
                fma2(acc1, e2[4 * i + 1], qa.y);                                 \
                fma2(acc2, e2[4 * i + 2], qb.x);                                 \
                fma2(acc3, e2[4 * i + 3], qb.y);                                 \
            }                                                                    \
            add2(acc0, acc2); add2(acc1, acc3);                                  \
            add2(acc0, acc1);                                                    \
            float v = (__uint_as_float((unsigned)acc0) +                         \
                       __uint_as_float((unsigned)(acc0 >> 32))) * ef;            \
            pbuf[(t + 1) & 1][k] = v;                                            \
            __syncthreads();                                                     \
            ehc = ehn;                                                           \
            t++;                                                                 \
        }

        while (t + 2 <= L) {
            STEP(hx, hy);    // step t:   loads h[t+2] into hx, exps hy=h[t+1]
            STEP(hy, hx);    // step t+1: loads h[t+3] into hy, exps hx=h[t+2]
        }
        if (t < L) STEP(hx, hy);
#undef STEP

        // out[b] = C + log( sum_k P_L[k] * E[EOS,k] )
        float val = pbuf[t & 1][k] * eEOS;
        #pragma unroll
        for (int o = 16; o > 0; o >>= 1)
            val += __shfl_xor_sync(0xffffffffu, val, o);
        if (lane == 0) fred[w] = val;
        __syncthreads();
        if (k == 0)
            out[b] = C + __logf(fred[0] + fred[1] + fred[2] + fred[3]);
        // pbuf reuse is safe: all reads of this batch's state precede the
        // __syncthreads() above; next batch's first write follows its peel sync.
    }
}

extern "C" void kernel_launch(void* const* d_in, const int* in_sizes, int n_in,
                              void* d_out, int out_size) {
    const float* h     = (const float*)d_in[0];
    const float* trans = (const float*)d_in[1];
    const float* mask  = (const float*)d_in[2];
    float* out = (float*)d_out;
    (void)in_sizes; (void)n_in; (void)out_size;

    prep_kernel<<<65, 256>>>(trans, mask);
    crf_main_kernel<<<NCTA, Kq>>>(h, out);
}

// round 12
// speedup vs baseline: 1.5601x; 1.0321x over previous
#include <cuda_runtime.h>
#include <cuda_bf16.h>

#define Bq 256
#define Tq 512
#define Kq 128
#define SOS 0
#define EOSI 1
#define NCTA 148   // <= GB300 SM count: every CTA lands on its own SM (wave 1)
#define NSOLO 40   // 40 solo + 108 sequential pairs = 256 batches

__device__ float g_E[Kq * Kq];    // exp(trans), row-major
__device__ float g_ET[Kq * Kq];   // transpose of g_E
__device__ int   g_perm[Bq];      // batch index sorted by descending length
__device__ int   g_len[Bq];       // sequence length per batch

// ---------------- prep: E, E^T, lengths, rank permutation ----------------
__global__ void prep_kernel(const float* __restrict__ trans,
                            const float* __restrict__ mask) {
    if (blockIdx.x < 64) {
        int i = blockIdx.x * 256 + threadIdx.x;
        float v = expf(trans[i]);          // exp(-10000) -> exactly 0
        g_E[i] = v;
        int r = i >> 7, cc = i & 127;
        g_ET[cc * Kq + r] = v;
    } else {
        __shared__ int slen[Bq];
        int tid = threadIdx.x, w = tid >> 5, lane = tid & 31;
        for (int r = w; r < Bq; r += 8) {
            float s = 0.f;
            const float* mr = mask + (size_t)r * Tq;
            for (int i = lane; i < Tq; i += 32) s += mr[i];
            #pragma unroll
            for (int o = 16; o > 0; o >>= 1) s += __shfl_xor_sync(0xffffffffu, s, o);
            if (lane == 0) slen[r] = (int)(s + 0.5f);
        }
        __syncthreads();
        int L = slen[tid];
        g_len[tid] = L;
        int rank = 0;
        for (int j = 0; j < Bq; j++) {
            int Lj = slen[j];
            rank += (Lj > L) || (Lj == L && j < tid);
        }
        g_perm[rank] = tid;
    }
}

__device__ __forceinline__ unsigned long long pk2(float a, float b) {
    return (unsigned long long)__float_as_uint(a) |
           ((unsigned long long)__float_as_uint(b) << 32);
}
__device__ __forceinline__ void fma2(unsigned long long& d,
                                     unsigned long long a, unsigned long long b) {
    asm("fma.rn.f32x2 %0, %1, %2, %0;" : "+l"(d) : "l"(a), "l"(b));
}
__device__ __forceinline__ void add2(unsigned long long& d, unsigned long long a) {
    asm("add.rn.f32x2 %0, %0, %1;" : "+l"(d) : "l"(a));
}

// full 128-wide dot of reg-row e2[] with shared vector pu[]; also returns pivot=vec[2]
#define DOT128(VRES, PIVOT, PU)                                                  \
    {                                                                            \
        ulonglong2 q0 = (PU)[0];                                                 \
        PIVOT = __uint_as_float((unsigned)q0.y);                                 \
        unsigned long long acc0 = 0, acc1 = 0, acc2 = 0, acc3 = 0;               \
        fma2(acc0, e2[0], q0.x);                                                 \
        fma2(acc1, e2[1], q0.y);                                                 \
        {                                                                        \
            ulonglong2 qb0 = (PU)[1];                                            \
            fma2(acc2, e2[2], qb0.x);                                            \
            fma2(acc3, e2[3], qb0.y);                                            \
        }                                                                        \
        _Pragma("unroll")                                                        \
        for (int ii = 1; ii < 16; ii++) {                                        \
            ulonglong2 qa = (PU)[2 * ii];                                        \
            ulonglong2 qb = (PU)[2 * ii + 1];                                    \
            fma2(acc0, e2[4 * ii],     qa.x);                                    \
            fma2(acc1, e2[4 * ii + 1], qa.y);                                    \
            fma2(acc2, e2[4 * ii + 2], qb.x);                                    \
            fma2(acc3, e2[4 * ii + 3], qb.y);                                    \
        }                                                                        \
        add2(acc0, acc2); add2(acc1, acc3);                                      \
        add2(acc0, acc1);                                                        \
        VRES = __uint_as_float((unsigned)acc0) +                                 \
               __uint_as_float((unsigned)(acc0 >> 32));                          \
    }

// ---------------- main CRF scan: fwd+bwd half-chains per batch, 1 CTA/SM ------------
__global__ void __launch_bounds__(256, 1) crf_main_kernel(
    const float* __restrict__ h, float* __restrict__ out)
{
    int c = blockIdx.x;
    int tid = threadIdx.x;
    bool isF = tid < 128;            // warps 0-3 forward, 4-7 backward
    int k = tid & 127;
    int lane = tid & 31, w4 = (tid >> 5) & 3;

    int nb, r0, r1;
    if (c < NSOLO) { nb = 1; r0 = c;  r1 = 0; }
    else           { nb = 2; r0 = c;  r1 = 295 - c; }   // pairs (c, 295-c)

    __shared__ __align__(16) float pbuf[2][Kq];   // forward state
    __shared__ __align__(16) float qbuf[2][Kq];   // backward w vectors
    __shared__ __align__(16) float qres[Kq];
    __shared__ float fred[4];
    __shared__ float sCb;

    // this thread's matrix row: E row k (fwd) or E^T row k (bwd)
    unsigned long long e2[Kq / 2];
    {
        const float4* er = reinterpret_cast<const float4*>(
            (isF ? g_E : g_ET) + k * Kq);
        #pragma unroll
        for (int i = 0; i < Kq / 4; i++) {
            float4 f = er[i];
            e2[2 * i]     = pk2(f.x, f.y);
            e2[2 * i + 1] = pk2(f.z, f.w);
        }
    }
    float uk = g_E[EOSI * Kq + k];   // u[k] = E[EOS,k] (backward init)

    for (int bi = 0; bi < nb; bi++) {
        int b = g_perm[bi == 0 ? r0 : r1] & (Bq - 1);
        int L = g_len[b];
        int m = (L + 1) >> 1;        // forward steps (>=1); backward = L-m

        const float* hb = h + (size_t)b * Tq * Kq + k;
        float Cacc = 0.0f;

        if (isF) {
            // ---------------- forward: p_m = M_{m-1}...M_0 p_0 ----------------
            float ha0 = hb[0];
            float ha1 = hb[(size_t)1 * Kq];
            float ha2 = hb[(size_t)2 * Kq];

            float ehc = __expf(ha0);
            pbuf[1][k] = __uint_as_float((unsigned)e2[0]) * ehc;  // E[k,SOS]*e^{h0}
            asm volatile("bar.sync 1, 128;" ::: "memory");

            ehc = __expf(ha1);
            float hy = ha2, hx = 0.f;
            int t = 1;

#define STEP_F(LOADR, EXPR)                                                      \
            {                                                                    \
                int tp = t + 2;                                                  \
                LOADR = (tp < Tq) ? hb[(size_t)tp * Kq] : 0.f;                   \
                float ehn = __expf(EXPR);                                        \
                const ulonglong2* pu =                                           \
                    reinterpret_cast<const ulonglong2*>(pbuf[t & 1]);            \
                float v, pivot;                                                  \
                DOT128(v, pivot, pu);                                            \
                float ef = __fdividef(ehc, pivot);                               \
                Cacc += __logf(pivot);                                           \
                pbuf[(t + 1) & 1][k] = v * ef;                                   \
                asm volatile("bar.sync 1, 128;" ::: "memory");                   \
                ehc = ehn;                                                       \
                t++;                                                             \
            }
            while (t + 2 <= m) { STEP_F(hx, hy); STEP_F(hy, hx); }
            if (t < m) STEP_F(hx, hy);
#undef STEP_F
        } else {
            // ---------------- backward: q^T = u^T M_{L-1}...M_m ----------------
            int cnt = L - m;                 // = L>>1
            float v = uk;
            float pivot = 1.0f;
            if (cnt > 0) {
                int s = L - 1;
                float ehc = __expf(hb[(size_t)s * Kq]);
                float hy = (s - 1 >= 0) ? hb[(size_t)(s - 1) * Kq] : 0.f;
                float hx = 0.f;
                int i = 0;

#define STEP_B(LOADR, EXPR)                                                      \
                {                                                                \
                    int sp = s - 2;                                              \
                    LOADR = (sp >= 0) ? hb[(size_t)sp * Kq] : 0.f;               \
                    float ehn = __expf(EXPR);                                    \
                    float ef = __fdividef(ehc, pivot);                           \
                    Cacc += __logf(pivot);                                       \
                    qbuf[i & 1][k] = v * ef;                                     \
                    asm volatile("bar.sync 2, 128;" ::: "memory");               \
                    const ulonglong2* pu =                                       \
                        reinterpret_cast<const ulonglong2*>(qbuf[i & 1]);        \
                    DOT128(v, pivot, pu);                                        \
                    ehc = ehn;                                                   \
                    i++; s--;                                                    \
                }
                while (i + 2 <= cnt) { STEP_B(hx, hy); STEP_B(hy, hx); }
                if (i < cnt) STEP_B(hx, hy);
#undef STEP_B
            }
            qres[k] = v;
            if (k == 0) sCb = Cacc;
        }

        __syncthreads();   // both chains done; qres, sCb, pbuf[m&1] visible

        // out[b] = C_f + C_b + log( sum_k p_m[k] * q_m[k] )
        if (isF) {
            float val = pbuf[m & 1][k] * qres[k];
            #pragma unroll
            for (int o = 16; o > 0; o >>= 1)
                val += __shfl_xor_sync(0xffffffffu, val, o);
            if (lane == 0) fred[w4] = val;
            asm volatile("bar.sync 1, 128;" ::: "memory");
            if (tid == 0)
                out[b] = Cacc + sCb +
                         __logf(fred[0] + fred[1] + fred[2] + fred[3]);
        }
        __syncthreads();   // protect shared reuse for next batch
    }
}

extern "C" void kernel_launch(void* const* d_in, const int* in_sizes, int n_in,
                              void* d_out, int out_size) {
    const float* h     = (const float*)d_in[0];
    const float* trans = (const float*)d_in[1];
    const float* mask  = (const float*)d_in[2];
    float* out = (float*)d_out;
    (void)in_sizes; (void)n_in; (void)out_size;

    prep_kernel<<<65, 256>>>(trans, mask);
    crf_main_kernel<<<NCTA, 256>>>(h, out);
}

// round 14
// speedup vs baseline: 1.5651x; 1.0032x over previous
#include <cuda_runtime.h>
#include <cuda_bf16.h>

#define Bq 256
#define Tq 512
#define Kq 128
#define SOS 0
#define EOSI 1
#define NCTA 148   // <= GB300 SM count: every CTA lands on its own SM (wave 1)
#define NSOLO 40   // 40 solo + 108 sequential pairs = 256 batches

__device__ float g_E[Kq * Kq];    // exp(trans), row-major
__device__ float g_ET[Kq * Kq];   // transpose of g_E
__device__ int   g_perm[Bq];      // batch index sorted by descending length
__device__ int   g_len[Bq];       // sequence length per batch

// ---------------- prep: E, E^T, lengths, rank permutation ----------------
__global__ void prep_kernel(const float* __restrict__ trans,
                            const float* __restrict__ mask) {
    if (blockIdx.x < 64) {
        int i = blockIdx.x * 256 + threadIdx.x;
        float v = expf(trans[i]);          // exp(-10000) -> exactly 0
        g_E[i] = v;
        int r = i >> 7, cc = i & 127;
        g_ET[cc * Kq + r] = v;
    } else {
        __shared__ int slen[Bq];
        int tid = threadIdx.x, w = tid >> 5, lane = tid & 31;
        for (int r = w; r < Bq; r += 8) {
            float s = 0.f;
            const float* mr = mask + (size_t)r * Tq;
            for (int i = lane; i < Tq; i += 32) s += mr[i];
            #pragma unroll
            for (int o = 16; o > 0; o >>= 1) s += __shfl_xor_sync(0xffffffffu, s, o);
            if (lane == 0) slen[r] = (int)(s + 0.5f);
        }
        __syncthreads();
        int L = slen[tid];
        g_len[tid] = L;
        int rank = 0;
        for (int j = 0; j < Bq; j++) {
            int Lj = slen[j];
            rank += (Lj > L) || (Lj == L && j < tid);
        }
        g_perm[rank] = tid;
    }
}

__device__ __forceinline__ unsigned long long pk2(float a, float b) {
    return (unsigned long long)__float_as_uint(a) |
           ((unsigned long long)__float_as_uint(b) << 32);
}
__device__ __forceinline__ void fma2(unsigned long long& d,
                                     unsigned long long a, unsigned long long b) {
    asm("fma.rn.f32x2 %0, %1, %2, %0;" : "+l"(d) : "l"(a), "l"(b));
}
__device__ __forceinline__ void add2(unsigned long long& d, unsigned long long a) {
    asm("add.rn.f32x2 %0, %0, %1;" : "+l"(d) : "l"(a));
}

// full 128-wide dot of reg-row e2[] with shared vector pu[]; also returns pivot=vec[2]
#define DOT128(VRES, PIVOT, PU)                                                  \
    {                                                                            \
        ulonglong2 q0 = (PU)[0];                                                 \
        PIVOT = __uint_as_float((unsigned)q0.y);                                 \
        unsigned long long acc0 = 0, acc1 = 0, acc2 = 0, acc3 = 0;               \
        fma2(acc0, e2[0], q0.x);                                                 \
        fma2(acc1, e2[1], q0.y);                                                 \
        {                                                                        \
            ulonglong2 qb0 = (PU)[1];                                            \
            fma2(acc2, e2[2], qb0.x);                                            \
            fma2(acc3, e2[3], qb0.y);                                            \
        }                                                                        \
        _Pragma("unroll")                                                        \
        for (int ii = 1; ii < 16; ii++) {                                        \
            ulonglong2 qa = (PU)[2 * ii];                                        \
            ulonglong2 qb = (PU)[2 * ii + 1];                                    \
            fma2(acc0, e2[4 * ii],     qa.x);                                    \
            fma2(acc1, e2[4 * ii + 1], qa.y);                                    \
            fma2(acc2, e2[4 * ii + 2], qb.x);                                    \
            fma2(acc3, e2[4 * ii + 3], qb.y);                                    \
        }                                                                        \
        add2(acc0, acc2); add2(acc1, acc3);                                      \
        add2(acc0, acc1);                                                        \
        VRES = __uint_as_float((unsigned)acc0) +                                 \
               __uint_as_float((unsigned)(acc0 >> 32));                          \
    }

// ---------------- main CRF scan: fwd+bwd half-chains per batch, 1 CTA/SM ------------
__global__ void __launch_bounds__(256, 1) crf_main_kernel(
    const float* __restrict__ h, float* __restrict__ out)
{
    int c = blockIdx.x;
    int tid = threadIdx.x;
    bool isF = tid < 128;            // warps 0-3 forward, 4-7 backward
    int k = tid & 127;
    int lane = tid & 31, w4 = (tid >> 5) & 3;

    int nb, r0, r1;
    if (c < NSOLO) { nb = 1; r0 = c;  r1 = 0; }
    else           { nb = 2; r0 = c;  r1 = 295 - c; }   // pairs (c, 295-c)

    __shared__ __align__(16) float pbuf[2][Kq];   // forward state
    __shared__ __align__(16) float qbuf[2][Kq];   // backward w vectors
    __shared__ __align__(16) float qres[Kq];
    __shared__ float fred[4];
    __shared__ float sCb;

    // this thread's matrix row: E row k (fwd) or E^T row k (bwd)
    unsigned long long e2[Kq / 2];
    {
        const float4* er = reinterpret_cast<const float4*>(
            (isF ? g_E : g_ET) + k * Kq);
        #pragma unroll
        for (int i = 0; i < Kq / 4; i++) {
            float4 f = er[i];
            e2[2 * i]     = pk2(f.x, f.y);
            e2[2 * i + 1] = pk2(f.z, f.w);
        }
    }
    float uk = g_E[EOSI * Kq + k];   // u[k] = E[EOS,k] (backward init)

    for (int bi = 0; bi < nb; bi++) {
        int b = g_perm[bi == 0 ? r0 : r1] & (Bq - 1);
        int L = g_len[b];
        int m = (L + 1) >> 1;        // forward steps (>=1); backward = L-m

        const float* hb = h + (size_t)b * Tq * Kq + k;
        float Cacc = 0.0f;

        if (isF) {
            // ---------------- forward: p_m = M_{m-1}...M_0 p_0 ----------------
            float ha0 = hb[0];
            float ha1 = hb[(size_t)1 * Kq];
            float ha2 = hb[(size_t)2 * Kq];

            float ehc = __expf(ha0);
            pbuf[1][k] = __uint_as_float((unsigned)e2[0]) * ehc;  // E[k,SOS]*e^{h0}
            asm volatile("bar.sync 1, 128;" ::: "memory");

            ehc = __expf(ha1);
            float hy = ha2, hx = 0.f;
            int t = 1;

#define STEP_F(LOADR, EXPR)                                                      \
            {                                                                    \
                int tp = t + 2;                                                  \
                LOADR = (tp < Tq) ? hb[(size_t)tp * Kq] : 0.f;                   \
                float ehn = __expf(EXPR);                                        \
                const ulonglong2* pu =                                           \
                    reinterpret_cast<const ulonglong2*>(pbuf[t & 1]);            \
                float v, pivot;                                                  \
                DOT128(v, pivot, pu);                                            \
                float ef = __fdividef(ehc, pivot);                               \
                Cacc += __logf(pivot);                                           \
                pbuf[(t + 1) & 1][k] = v * ef;                                   \
                asm volatile("bar.sync 1, 128;" ::: "memory");                   \
                ehc = ehn;                                                       \
                t++;                                                             \
            }
            while (t + 2 <= m) { STEP_F(hx, hy); STEP_F(hy, hx); }
            if (t < m) STEP_F(hx, hy);
#undef STEP_F
        } else {
            // ---------------- backward: q^T = u^T M_{L-1}...M_m ----------------
            int cnt = L - m;                 // = L>>1
            float v = uk;
            float pivot = 1.0f;
            if (cnt > 0) {
                int s = L - 1;
                float ehc = __expf(hb[(size_t)s * Kq]);
                float hy = (s - 1 >= 0) ? hb[(size_t)(s - 1) * Kq] : 0.f;
                float hx = 0.f;
                int i = 0;

#define STEP_B(LOADR, EXPR)                                                      \
                {                                                                \
                    int sp = s - 2;                                              \
                    LOADR = (sp >= 0) ? hb[(size_t)sp * Kq] : 0.f;               \
                    float ehn = __expf(EXPR);                                    \
                    float ef = __fdividef(ehc, pivot);                           \
                    Cacc += __logf(pivot);                                       \
                    qbuf[i & 1][k] = v * ef;                                     \
                    asm volatile("bar.sync 2, 128;" ::: "memory");               \
                    const ulonglong2* pu =                                       \
                        reinterpret_cast<const ulonglong2*>(qbuf[i & 1]);        \
                    DOT128(v, pivot, pu);                                        \
                    ehc = ehn;                                                   \
                    i++; s--;                                                    \
                }
                while (i + 2 <= cnt) { STEP_B(hx, hy); STEP_B(hy, hx); }
                if (i < cnt) STEP_B(hx, hy);
#undef STEP_B
            }
            qres[k] = v;
            if (k == 0) sCb = Cacc;
        }

        __syncthreads();   // both chains done; qres, sCb, pbuf[m&1] visible

        // out[b] = C_f + C_b + log( sum_k p_m[k] * q_m[k] )
        if (isF) {
            float val = pbuf[m & 1][k] * qres[k];
            #pragma unroll
            for (int o = 16; o > 0; o >>= 1)
                val += __shfl_xor_sync(0xffffffffu, val, o);
            if (lane == 0) fred[w4] = val;
            asm volatile("bar.sync 1, 128;" ::: "memory");
            if (tid == 0)
                out[b] = Cacc + sCb +
                         __logf(fred[0] + fred[1] + fred[2] + fred[3]);
        }
        __syncthreads();   // protect shared reuse for next batch
    }
}

extern "C" void kernel_launch(void* const* d_in, const int* in_sizes, int n_in,
                              void* d_out, int out_size) {
    const float* h     = (const float*)d_in[0];
    const float* trans = (const float*)d_in[1];
    const float* mask  = (const float*)d_in[2];
    float* out = (float*)d_out;
    (void)in_sizes; (void)n_in; (void)out_size;

    prep_kernel<<<65, 256>>>(trans, mask);
    crf_main_kernel<<<NCTA, 256>>>(h, out);
}

// round 15
// speedup vs baseline: 1.6846x; 1.0763x over previous
#include <cuda_runtime.h>
#include <cuda_bf16.h>

#define Bq 256
#define Tq 512
#define Kq 128
#define SOS 0
#define EOSI 1
#define NCTA 148   // <= GB300 SM count: every CTA lands on its own SM (wave 1)
#define NSOLO 40   // 40 solo + 108 sequential pairs = 256 batches

__device__ float g_E[Kq * Kq];    // exp(trans), row-major
__device__ float g_ET[Kq * Kq];   // transpose of g_E
__device__ int   g_perm[Bq];      // batch index sorted by descending length
__device__ int   g_len[Bq];       // sequence length per batch

// ---------------- prep: E, E^T, lengths, rank permutation ----------------
__global__ void prep_kernel(const float* __restrict__ trans,
                            const float* __restrict__ mask) {
    if (blockIdx.x < 64) {
        int i = blockIdx.x * 256 + threadIdx.x;
        float v = expf(trans[i]);          // exp(-10000) -> exactly 0
        g_E[i] = v;
        int r = i >> 7, cc = i & 127;
        g_ET[cc * Kq + r] = v;
    } else {
        __shared__ int slen[Bq];
        int tid = threadIdx.x, w = tid >> 5, lane = tid & 31;
        for (int r = w; r < Bq; r += 8) {
            float s = 0.f;
            const float* mr = mask + (size_t)r * Tq;
            for (int i = lane; i < Tq; i += 32) s += mr[i];
            #pragma unroll
            for (int o = 16; o > 0; o >>= 1) s += __shfl_xor_sync(0xffffffffu, s, o);
            if (lane == 0) slen[r] = (int)(s + 0.5f);
        }
        __syncthreads();
        int L = slen[tid];
        g_len[tid] = L;
        int rank = 0;
        for (int j = 0; j < Bq; j++) {
            int Lj = slen[j];
            rank += (Lj > L) || (Lj == L && j < tid);
        }
        g_perm[rank] = tid;
    }
}

// bf16-vector dot: 16 LDS.128 deliver 128 bf16; even idx exact via SHF<<16,
// odd idx uses the raw word (neighbor bits = <2^-8 mantissa noise, common-mode
// cancels through pivot normalization). fp32 accumulate, 8 chains.
#define DOTB(VRES, PIVOT, PU)                                                    \
    {                                                                            \
        uint4 r0 = (PU)[0];                                                      \
        PIVOT = __uint_as_float(r0.y << 16);             /* p[2], exact */       \
        float a0, a1, a2, a3, a4, a5, a6, a7;                                    \
        a0 = e[0] * __uint_as_float(r0.x << 16);                                 \
        a1 = e[1] * __uint_as_float(r0.x);                                       \
        a2 = e[2] * __uint_as_float(r0.y << 16);                                 \
        a3 = e[3] * __uint_as_float(r0.y);                                       \
        a4 = e[4] * __uint_as_float(r0.z << 16);                                 \
        a5 = e[5] * __uint_as_float(r0.z);                                       \
        a6 = e[6] * __uint_as_float(r0.w << 16);                                 \
        a7 = e[7] * __uint_as_float(r0.w);                                       \
        _Pragma("unroll")                                                        \
        for (int ii = 1; ii < 16; ii++) {                                        \
            uint4 r = (PU)[ii];                                                  \
            a0 = fmaf(e[8 * ii],     __uint_as_float(r.x << 16), a0);            \
            a1 = fmaf(e[8 * ii + 1], __uint_as_float(r.x),       a1);            \
            a2 = fmaf(e[8 * ii + 2], __uint_as_float(r.y << 16), a2);            \
            a3 = fmaf(e[8 * ii + 3], __uint_as_float(r.y),       a3);            \
            a4 = fmaf(e[8 * ii + 4], __uint_as_float(r.z << 16), a4);            \
            a5 = fmaf(e[8 * ii + 5], __uint_as_float(r.z),       a5);            \
            a6 = fmaf(e[8 * ii + 6], __uint_as_float(r.w << 16), a6);            \
            a7 = fmaf(e[8 * ii + 7], __uint_as_float(r.w),       a7);            \
        }                                                                        \
        VRES = ((a0 + a1) + (a2 + a3)) + ((a4 + a5) + (a6 + a7));                \
    }

// ---------------- main CRF scan: fwd+bwd half-chains, bf16 state, 1 CTA/SM ----------
__global__ void __launch_bounds__(256, 1) crf_main_kernel(
    const float* __restrict__ h, float* __restrict__ out)
{
    int c = blockIdx.x;
    int tid = threadIdx.x;
    bool isF = tid < 128;            // warps 0-3 forward, 4-7 backward
    int k = tid & 127;
    int lane = tid & 31, w4 = (tid >> 5) & 3;

    int nb, r0, r1;
    if (c < NSOLO) { nb = 1; r0 = c;  r1 = 0; }
    else           { nb = 2; r0 = c;  r1 = 295 - c; }   // pairs (c, 295-c)

    __shared__ __align__(16) __nv_bfloat16 pbuf[2][Kq];   // forward state (bf16)
    __shared__ __align__(16) __nv_bfloat16 qbuf[2][Kq];   // backward state (bf16)
    __shared__ __align__(16) float qres[Kq];
    __shared__ float fred[4];
    __shared__ float sCb;

    // this thread's matrix row, scalar fp32: E row k (fwd) or E^T row k (bwd)
    float e[Kq];
    {
        const float4* er = reinterpret_cast<const float4*>(
            (isF ? g_E : g_ET) + k * Kq);
        #pragma unroll
        for (int i = 0; i < Kq / 4; i++) {
            float4 f = er[i];
            e[4 * i] = f.x; e[4 * i + 1] = f.y;
            e[4 * i + 2] = f.z; e[4 * i + 3] = f.w;
        }
    }
    float uk = g_E[EOSI * Kq + k];   // u[k] = E[EOS,k] (backward init)

    for (int bi = 0; bi < nb; bi++) {
        int b = g_perm[bi == 0 ? r0 : r1] & (Bq - 1);
        int L = g_len[b];
        int m = (L + 1) >> 1;        // forward steps (>=1); backward = L-m

        const float* hb = h + (size_t)b * Tq * Kq + k;
        float Cacc = 0.0f;

        if (isF) {
            // ---------------- forward: p_m = M_{m-1}...M_0 p_0 ----------------
            float ha0 = hb[0];
            float ha1 = hb[(size_t)1 * Kq];
            float ha2 = hb[(size_t)2 * Kq];

            float ehc = __expf(ha0);
            pbuf[1][k] = __float2bfloat16_rn(e[0] * ehc);   // E[k,SOS]*e^{h0}
            asm volatile("bar.sync 1, 128;" ::: "memory");

            ehc = __expf(ha1);
            float hy = ha2, hx = 0.f;
            int t = 1;

#define STEP_F(LOADR, EXPR)                                                      \
            {                                                                    \
                int tp = t + 2;                                                  \
                LOADR = (tp < Tq) ? hb[(size_t)tp * Kq] : 0.f;                   \
                float ehn = __expf(EXPR);                                        \
                const uint4* pu =                                                \
                    reinterpret_cast<const uint4*>(pbuf[t & 1]);                 \
                float v, pivot;                                                  \
                DOTB(v, pivot, pu);                                              \
                float ef = __fdividef(ehc, pivot);                               \
                Cacc += __logf(pivot);                                           \
                pbuf[(t + 1) & 1][k] = __float2bfloat16_rn(v * ef);              \
                asm volatile("bar.sync 1, 128;" ::: "memory");                   \
                ehc = ehn;                                                       \
                t++;                                                             \
            }
            while (t + 2 <= m) { STEP_F(hx, hy); STEP_F(hy, hx); }
            if (t < m) STEP_F(hx, hy);
#undef STEP_F
        } else {
            // ---------------- backward: q^T = u^T M_{L-1}...M_m ----------------
            int cnt = L - m;                 // = L>>1
            float v = uk;
            float pivot = 1.0f;
            if (cnt > 0) {
                int s = L - 1;
                float ehc = __expf(hb[(size_t)s * Kq]);
                float hy = (s - 1 >= 0) ? hb[(size_t)(s - 1) * Kq] : 0.f;
                float hx = 0.f;
                int i = 0;

#define STEP_B(LOADR, EXPR)                                                      \
                {                                                                \
                    int sp = s - 2;                                              \
                    LOADR = (sp >= 0) ? hb[(size_t)sp * Kq] : 0.f;               \
                    float ehn = __expf(EXPR);                                    \
                    float ef = __fdividef(ehc, pivot);                           \
                    Cacc += __logf(pivot);                                       \
                    qbuf[i & 1][k] = __float2bfloat16_rn(v * ef);                \
                    asm volatile("bar.sync 2, 128;" ::: "memory");               \
                    const uint4* pu =                                            \
                        reinterpret_cast<const uint4*>(qbuf[i & 1]);             \
                    DOTB(v, pivot, pu);                                          \
                    ehc = ehn;                                                   \
                    i++; s--;                                                    \
                }
                while (i + 2 <= cnt) { STEP_B(hx, hy); STEP_B(hy, hx); }
                if (i < cnt) STEP_B(hx, hy);
#undef STEP_B
            }
            qres[k] = v;                 // final backward vector kept in fp32
            if (k == 0) sCb = Cacc;
        }

        __syncthreads();   // both chains done; qres, sCb, pbuf[m&1] visible

        // out[b] = C_f + C_b + log( sum_k p_m[k] * q_m[k] )
        if (isF) {
            float val = __bfloat162float(pbuf[m & 1][k]) * qres[k];
            #pragma unroll
            for (int o = 16; o > 0; o >>= 1)
                val += __shfl_xor_sync(0xffffffffu, val, o);
            if (lane == 0) fred[w4] = val;
            asm volatile("bar.sync 1, 128;" ::: "memory");
            if (tid == 0)
                out[b] = Cacc + sCb +
                         __logf(fred[0] + fred[1] + fred[2] + fred[3]);
        }
        __syncthreads();   // protect shared reuse for next batch
    }
}

extern "C" void kernel_launch(void* const* d_in, const int* in_sizes, int n_in,
                              void* d_out, int out_size) {
    const float* h     = (const float*)d_in[0];
    const float* trans = (const float*)d_in[1];
    const float* mask  = (const float*)d_in[2];
    float* out = (float*)d_out;
    (void)in_sizes; (void)n_in; (void)out_size;

    prep_kernel<<<65, 256>>>(trans, mask);
    crf_main_kernel<<<NCTA, 256>>>(h, out);
}